// round 10
// baseline (speedup 1.0000x reference)
#include <cuda_runtime.h>

#define MAXN 6016
#define NB   94                     // max number of 64-box blocks
#define TRI  (NB * (NB + 1) / 2)    // 4465 upper-triangle tiles
typedef unsigned long long u64;

// Scratch (device globals: allocation is banned; zero-initialized at load)
__device__ float4 g_sboxes[MAXN];
__device__ int    g_rank[MAXN];
__device__ u64    g_plist[MAXN];                // packed (score_bits<<32)|idx
__device__ u64    g_maskT[(size_t)NB * MAXN];   // TRANSPOSED: [colblock][row]
__device__ u64    g_nzb[TRI];                   // per-tile nonzero-row bitmaps
__device__ int    g_cnt;  // #prefix boxes; reset at end of scan_kernel

#define SWEEP_WARPS 30
#define SCAN_THREADS 1024

__device__ __forceinline__ int tri_start(int r) { return r * NB - (r * (r - 1)) / 2; }

__device__ __forceinline__ unsigned smem_u32(const void* p) {
    return (unsigned)__cvta_generic_to_shared(p);
}
__device__ __forceinline__ void cp_async16(unsigned dst, const u64* src) {
    asm volatile("cp.async.cg.shared.global [%0], [%1], 16;" :: "r"(dst), "l"(src));
}
#define CP_COMMIT() asm volatile("cp.async.commit_group;" ::: "memory")
#define CP_WAIT1()  asm volatile("cp.async.wait_group 1;" ::: "memory")

__device__ __forceinline__ u64 redux_or64(u64 v) {
    unsigned lo = __reduce_or_sync(0xffffffffu, (unsigned)v);
    unsigned hi = __reduce_or_sync(0xffffffffu, (unsigned)(v >> 32));
    return (u64)lo | ((u64)hi << 32);
}

// ---------------------------------------------------------------------------
// 0) Compact prefix boxes (s >= 0.6) into g_plist.
// ---------------------------------------------------------------------------
__global__ void compact_kernel(const float* __restrict__ scores, int n) {
    int i = blockIdx.x * blockDim.x + threadIdx.x;
    if (i >= n) return;
    float s = scores[i];
    if (s >= 0.6f) {
        int p = atomicAdd(&g_cnt, 1);
        g_plist[p] = ((u64)__float_as_uint(s) << 32) | (unsigned)i;
    }
}

// ---------------------------------------------------------------------------
// 1) Rank within the prefix subset (== global rank for prefix boxes).
// ---------------------------------------------------------------------------
__global__ void rank_kernel(const float* __restrict__ boxes, int n) {
    const int w    = (blockIdx.x * blockDim.x + threadIdx.x) >> 5;
    const int lane = threadIdx.x & 31;
    const int m = g_cnt;
    if (w >= m) return;
    const u64 me = g_plist[w];
    const unsigned sb = (unsigned)(me >> 32);
    const unsigned ib = (unsigned)me;
    int cnt = 0;
    for (int j = lane; j < m; j += 32) {
        u64 e = g_plist[j];
        unsigned sj = (unsigned)(e >> 32);
        unsigned ij = (unsigned)e;
        cnt += (int)((sj > sb) | ((sj == sb) & (ij < ib)));
    }
    #pragma unroll
    for (int o = 16; o; o >>= 1) cnt += __shfl_down_sync(0xffffffffu, cnt, o);
    if (lane == 0) {
        g_sboxes[cnt] = ((const float4*)boxes)[ib];
        g_rank[ib]    = cnt;
    }
}

// ---------------------------------------------------------------------------
// 2) Suppression mask + per-tile nonzero-row bitmap. Triangular 1D grid.
//    Division-free exact threshold: iou>0.5 <=> fma(-0.5,uni,inter)>0.
// ---------------------------------------------------------------------------
__global__ void mask_kernel(int n) {
    int m = g_cnt; if (m > n) m = n;
    const int mb = (m + 63) >> 6;

    // linear tile -> (rb, cb) with cb >= rb
    const int p = blockIdx.x;
    int rb = (int)((2.0f * NB + 1.0f
                    - sqrtf((2.0f * NB + 1.0f) * (2.0f * NB + 1.0f) - 8.0f * p)) * 0.5f);
    if (rb < 0) rb = 0;
    while (rb + 1 <= NB - 1 && tri_start(rb + 1) <= p) rb++;
    while (rb > 0 && tri_start(rb) > p) rb--;
    const int cb = rb + (p - tri_start(rb));
    if (rb >= mb || cb >= mb) return;

    const int t = threadIdx.x;                   // 0..63
    __shared__ float4   cbox[64];                // {cz, cw, -cx, -cy}
    __shared__ float    carea[64];
    __shared__ unsigned nzhalf[2];
    const int col0 = cb * 64;
    if (col0 + t < m) {
        float4 c = g_sboxes[col0 + t];
        cbox[t]  = make_float4(c.z, c.w, -c.x, -c.y);
        carea[t] = (c.z - c.x) * (c.w - c.y);
    } else {
        cbox[t]  = make_float4(-1e30f, -1e30f, -1e30f, -1e30f);  // -> IoU 0
        carea[t] = 0.f;
    }
    __syncthreads();

    const int row = rb * 64 + t;
    const float4 b   = g_sboxes[row];            // stale if row>=m; bits forced 0
    const float  bz  = b.z,  bw  = b.w;
    const float  nbx = -b.x, nby = -b.y;
    const float  barea = (b.z - b.x) * (b.w - b.y);

    u64 bits = 0ULL;
    #pragma unroll
    for (int k = 0; k < 64; k++) {
        float4 c  = cbox[k];
        float iw  = fmaxf(fminf(bz, c.x) + fminf(nbx, c.z), 0.f);
        float ih  = fmaxf(fminf(bw, c.y) + fminf(nby, c.w), 0.f);
        float inter = iw * ih;
        float uni   = (barea + carea[k]) - inter;
        if (fmaf(-0.5f, uni, inter) > 0.f) bits |= (1ULL << k);
    }
    if (cb == rb) bits &= ((~1ULL) << t);        // keep only cols > row
    if (row >= m) bits = 0ULL;
    g_maskT[(size_t)cb * MAXN + row] = bits;

    unsigned bal = __ballot_sync(0xffffffffu, bits != 0ULL);
    if ((t & 31) == 0) nzhalf[t >> 5] = bal;
    __syncthreads();
    if (t == 0) g_nzb[p] = (u64)nzhalf[0] | ((u64)nzhalf[1] << 32);
}

// ---------------------------------------------------------------------------
// 3) Greedy scan + finalize, one CTA / 32 warps, sparse sweep:
//    warp 31: serial resolve from prefetched diag slice; register-carried
//             block b -> column b+1 term from prefetched cross slice.
//    warp 30: cp.async distance-2 prefetch of diag/cross slices (4-slot ring).
//    warps 0..29: for each future column j, test nzb[b-1][j] & kept (1 LDS);
//             only on hit (~4% of tiles) gather the few nonzero words from L2.
//    NOTE: diag/cross MUST be 16B-aligned — cp.async 16B dst traps otherwise
//    (round-9 crash: odd TRI left them at offset 8 mod 16).
// ---------------------------------------------------------------------------
__global__ void scan_kernel(const float* __restrict__ scores,
                            float* __restrict__ out, int n) {
    __shared__ __align__(16) u64 diag[4][64];
    __shared__ __align__(16) u64 cross[4][64];
    __shared__ u64 nzb_s[TRI];         // ~35.7 KB
    __shared__ u64 remv[NB];
    __shared__ u64 keep[NB];

    const int t = threadIdx.x;
    const int warp = t >> 5, lane = t & 31;
    int m = g_cnt; if (m > n) m = n;
    const int mb = (m + 63) >> 6;
    const int tri_lim = tri_start(mb);

    for (int i = t; i < tri_lim; i += SCAN_THREADS) nzb_s[i] = g_nzb[i];
    if (t < NB) { remv[t] = 0ULL; keep[t] = 0ULL; }

    if (warp == 30) {                  // prime slices for iterations 0 and 1
        #pragma unroll
        for (int X = 0; X <= 1; X++) {
            if (X < mb) {
                cp_async16(smem_u32(&diag[X & 3][2 * lane]),
                           g_maskT + (size_t)X * MAXN + X * 64 + 2 * lane);
                if (X + 1 < mb)
                    cp_async16(smem_u32(&cross[X & 3][2 * lane]),
                               g_maskT + (size_t)(X + 1) * MAXN + X * 64 + 2 * lane);
            }
            CP_COMMIT();
        }
        CP_WAIT1();
    }
    __syncthreads();

    u64 carry = 0ULL;                  // resolve warp: block b-1 -> column b

    for (int b = 0; b < mb; b++) {
        if (warp == 31) {
            const int ts = tri_start(b);
            const u64* dcol = diag[b & 3];
            u64 kept = 0ULL;
            if (lane == 0) {
                u64 supp = remv[b] | carry;
                const int vr = m - b * 64;
                const u64 valid = (vr >= 64) ? ~0ULL : ((1ULL << vr) - 1ULL);
                u64 rem = nzb_s[ts] & ~supp & valid;   // nzb[b][b]
                while (rem) {
                    const int i = __ffsll((long long)rem) - 1;
                    rem &= rem - 1ULL;
                    if (!((supp >> i) & 1ULL)) {
                        supp |= dcol[i];
                        rem  &= ~supp;
                    }
                }
                kept = ~supp & valid;
                keep[b] = kept;
            }
            kept = __shfl_sync(0xffffffffu, kept, 0);
            carry = 0ULL;
            if (b + 1 < mb) {          // block b -> column b+1 (register carry)
                u64 nzc = nzb_s[ts + 1] & kept;        // nzb[b][b+1]
                u64 acc = 0ULL;
                if ((nzc >> lane) & 1ULL)        acc |= cross[b & 3][lane];
                if ((nzc >> (lane + 32)) & 1ULL) acc |= cross[b & 3][lane + 32];
                carry = redux_or64(acc);
            }
        } else if (warp == 30) {
            const int X = b + 2;
            if (X < mb) {
                cp_async16(smem_u32(&diag[X & 3][2 * lane]),
                           g_maskT + (size_t)X * MAXN + X * 64 + 2 * lane);
                if (X + 1 < mb)
                    cp_async16(smem_u32(&cross[X & 3][2 * lane]),
                               g_maskT + (size_t)(X + 1) * MAXN + X * 64 + 2 * lane);
            }
            CP_COMMIT();
            CP_WAIT1();
        } else if (b >= 1) {
            // Sparse lagged sweep: block b-1 -> columns j >= b+1
            const u64 kp = keep[b - 1];
            const int base = tri_start(b - 1) - (b - 1);
            const size_t roff = (size_t)(b - 1) * 64;
            for (int j = b + 1 + warp; j < mb; j += SWEEP_WARPS) {
                u64 nz = nzb_s[base + j] & kp;         // warp-uniform
                if (nz) {
                    const u64* col = g_maskT + (size_t)j * MAXN + roff;
                    u64 acc = 0ULL;
                    if ((nz >> lane) & 1ULL)        acc |= col[lane];
                    if ((nz >> (lane + 32)) & 1ULL) acc |= col[lane + 32];
                    u64 r = redux_or64(acc);
                    if (lane == 0) atomicOr(&remv[j], r);
                }
            }
        }
        __syncthreads();
    }

    // Fused finalize: out[i] = s if (s >= 0.6 && kept) else 0
    for (int i = t; i < n; i += SCAN_THREADS) {
        float s = scores[i];
        float v = 0.0f;
        if (s >= 0.6f) {
            int r = g_rank[i];
            if ((keep[r >> 6] >> (r & 63)) & 1ULL) v = s;
        }
        out[i] = v;
    }

    if (t == 0) g_cnt = 0;   // reset for next graph replay
}

// ---------------------------------------------------------------------------
extern "C" void kernel_launch(void* const* d_in, const int* in_sizes, int n_in,
                              void* d_out, int out_size) {
    const float* boxes  = (const float*)d_in[0];
    const float* scores = (const float*)d_in[1];
    const int n = in_sizes[1];                 // 6000

    compact_kernel<<<(n + 255) / 256, 256>>>(scores, n);

    rank_kernel<<<(n * 32 + 255) / 256, 256>>>(boxes, n);

    mask_kernel<<<TRI, 64>>>(n);

    scan_kernel<<<1, SCAN_THREADS>>>(scores, (float*)d_out, n);
}

// round 11
// speedup vs baseline: 1.1567x; 1.1567x over previous
#include <cuda_runtime.h>

#define MAXN 6016
#define NB   94                     // max number of 64-box blocks
#define TRI  (NB * (NB + 1) / 2)    // 4465 upper-triangle tiles
#define SPOOL 320                   // nonzero tiles preloaded into smem
typedef unsigned long long u64;

// Scratch (device globals: allocation is banned; zero-initialized at load)
__device__ float4 g_sboxes[MAXN];
__device__ int    g_rank[MAXN];
__device__ u64    g_plist[MAXN];        // packed (score_bits<<32)|idx
__device__ u64    g_pool[(size_t)TRI * 64];  // compacted nonzero tiles
__device__ int    g_slot[TRI];          // tile -> pool slot (-1 if zero tile)
__device__ u64    g_nzb[TRI];           // per-tile nonzero-row bitmaps
__device__ int    g_poolcnt;            // pool slots used; reset by scan
__device__ int    g_cnt;                // #prefix boxes; reset by scan

#define SCAN_THREADS 1024
// dynamic smem: pool | nzb | remv | keep | slot
#define SMEM_BYTES ((SPOOL * 64 + TRI + 2 * NB) * 8 + TRI * 4)

__device__ __forceinline__ int tri_start(int r) { return r * NB - (r * (r - 1)) / 2; }

__device__ __forceinline__ u64 redux_or64(u64 v) {
    unsigned lo = __reduce_or_sync(0xffffffffu, (unsigned)v);
    unsigned hi = __reduce_or_sync(0xffffffffu, (unsigned)(v >> 32));
    return (u64)lo | ((u64)hi << 32);
}

// ---------------------------------------------------------------------------
// 0) Compact prefix boxes (s >= 0.6) into g_plist.
// ---------------------------------------------------------------------------
__global__ void compact_kernel(const float* __restrict__ scores, int n) {
    int i = blockIdx.x * blockDim.x + threadIdx.x;
    if (i >= n) return;
    float s = scores[i];
    if (s >= 0.6f) {
        int p = atomicAdd(&g_cnt, 1);
        g_plist[p] = ((u64)__float_as_uint(s) << 32) | (unsigned)i;
    }
}

// ---------------------------------------------------------------------------
// 1) Rank within the prefix subset (== global rank for prefix boxes).
// ---------------------------------------------------------------------------
__global__ void rank_kernel(const float* __restrict__ boxes, int n) {
    const int w    = (blockIdx.x * blockDim.x + threadIdx.x) >> 5;
    const int lane = threadIdx.x & 31;
    const int m = g_cnt;
    if (w >= m) return;
    const u64 me = g_plist[w];
    const unsigned sb = (unsigned)(me >> 32);
    const unsigned ib = (unsigned)me;
    int cnt = 0;
    for (int j = lane; j < m; j += 32) {
        u64 e = g_plist[j];
        unsigned sj = (unsigned)(e >> 32);
        unsigned ij = (unsigned)e;
        cnt += (int)((sj > sb) | ((sj == sb) & (ij < ib)));
    }
    #pragma unroll
    for (int o = 16; o; o >>= 1) cnt += __shfl_down_sync(0xffffffffu, cnt, o);
    if (lane == 0) {
        g_sboxes[cnt] = ((const float4*)boxes)[ib];
        g_rank[ib]    = cnt;
    }
}

// ---------------------------------------------------------------------------
// 2) Suppression mask -> compact pool of NONZERO tiles + nzb bitmaps.
//    Slot order is nondeterministic (atomicAdd) but data is always read back
//    through g_slot, so kernel output is deterministic.
// ---------------------------------------------------------------------------
__global__ void mask_kernel(int n) {
    int m = g_cnt; if (m > n) m = n;
    const int mb = (m + 63) >> 6;

    // linear tile -> (rb, cb) with cb >= rb
    const int p = blockIdx.x;
    int rb = (int)((2.0f * NB + 1.0f
                    - sqrtf((2.0f * NB + 1.0f) * (2.0f * NB + 1.0f) - 8.0f * p)) * 0.5f);
    if (rb < 0) rb = 0;
    while (rb + 1 <= NB - 1 && tri_start(rb + 1) <= p) rb++;
    while (rb > 0 && tri_start(rb) > p) rb--;
    const int cb = rb + (p - tri_start(rb));
    if (rb >= mb || cb >= mb) return;

    const int t = threadIdx.x;                   // 0..63
    __shared__ float4   cbox[64];                // {cz, cw, -cx, -cy}
    __shared__ float    carea[64];
    __shared__ unsigned nzhalf[2];
    __shared__ int      slot_sh;
    const int col0 = cb * 64;
    if (col0 + t < m) {
        float4 c = g_sboxes[col0 + t];
        cbox[t]  = make_float4(c.z, c.w, -c.x, -c.y);
        carea[t] = (c.z - c.x) * (c.w - c.y);
    } else {
        cbox[t]  = make_float4(-1e30f, -1e30f, -1e30f, -1e30f);  // -> IoU 0
        carea[t] = 0.f;
    }
    __syncthreads();

    const int row = rb * 64 + t;
    const float4 b   = g_sboxes[row];            // stale if row>=m; bits forced 0
    const float  bz  = b.z,  bw  = b.w;
    const float  nbx = -b.x, nby = -b.y;
    const float  barea = (b.z - b.x) * (b.w - b.y);

    u64 bits = 0ULL;
    #pragma unroll
    for (int k = 0; k < 64; k++) {
        float4 c  = cbox[k];
        float iw  = fmaxf(fminf(bz, c.x) + fminf(nbx, c.z), 0.f);
        float ih  = fmaxf(fminf(bw, c.y) + fminf(nby, c.w), 0.f);
        float inter = iw * ih;
        float uni   = (barea + carea[k]) - inter;
        if (fmaf(-0.5f, uni, inter) > 0.f) bits |= (1ULL << k);
    }
    if (cb == rb) bits &= ((~1ULL) << t);        // keep only cols > row
    if (row >= m) bits = 0ULL;

    unsigned bal = __ballot_sync(0xffffffffu, bits != 0ULL);
    if ((t & 31) == 0) nzhalf[t >> 5] = bal;
    __syncthreads();
    if (t == 0) {
        u64 nzw = (u64)nzhalf[0] | ((u64)nzhalf[1] << 32);
        int s = (nzw != 0ULL) ? atomicAdd(&g_poolcnt, 1) : -1;
        g_nzb[p]  = nzw;
        g_slot[p] = s;
        slot_sh   = s;
    }
    __syncthreads();
    const int s = slot_sh;
    if (s >= 0) g_pool[(size_t)s * 64 + t] = bits;
}

// ---------------------------------------------------------------------------
// 3) Greedy scan + finalize. All nonzero mask tiles preloaded into smem once
//    (no per-iteration prefetch machinery, no exposed L2 latency). Per block:
//      warp 31: resolve(b) from smem pool; register carry b -> b+1 via the
//               cross tile (also smem).
//      warps 0..30: sparse lagged sweep block b-1 -> cols j >= b+1; one LDS
//               test per column, on-hit gather FROM SMEM + atomicOr.
//    One __syncthreads per block. L2 fallback only if pool > SPOOL tiles.
// ---------------------------------------------------------------------------
__global__ void scan_kernel(const float* __restrict__ scores,
                            float* __restrict__ out, int n) {
    extern __shared__ u64 dyn[];
    u64* pool_s = dyn;                       // SPOOL*64
    u64* nzb_s  = pool_s + SPOOL * 64;       // TRI
    u64* remv   = nzb_s + TRI;               // NB
    u64* keep   = remv + NB;                 // NB
    int* slot_s = (int*)(keep + NB);         // TRI

    const int t = threadIdx.x;
    const int warp = t >> 5, lane = t & 31;
    int m = g_cnt; if (m > n) m = n;
    const int mb = (m + 63) >> 6;
    const int tri_lim = tri_start(mb);

    // One-shot parallel preload of the entire working set into smem
    int pc = g_poolcnt; if (pc > SPOOL) pc = SPOOL;
    for (int i = t; i < pc * 64; i += SCAN_THREADS) pool_s[i] = g_pool[i];
    for (int i = t; i < tri_lim; i += SCAN_THREADS) {
        nzb_s[i]  = g_nzb[i];
        slot_s[i] = g_slot[i];
    }
    if (t < NB) { remv[t] = 0ULL; keep[t] = 0ULL; }
    __syncthreads();

    u64 carry = 0ULL;    // resolve warp: block b-1's contribution to block b

    for (int b = 0; b < mb; b++) {
        if (warp == 31) {
            const int tsb = tri_start(b);
            u64 kept = 0ULL;
            if (lane == 0) {
                u64 supp = remv[b] | carry;
                const int vr = m - b * 64;
                const u64 valid = (vr >= 64) ? ~0ULL : ((1ULL << vr) - 1ULL);
                u64 rem = nzb_s[tsb] & ~supp & valid;
                if (rem) {
                    const int ds = slot_s[tsb];
                    const u64* dt = (ds < SPOOL) ? pool_s + ds * 64
                                                 : g_pool + (size_t)ds * 64;
                    while (rem) {
                        const int i = __ffsll((long long)rem) - 1;
                        rem &= rem - 1ULL;
                        if (!((supp >> i) & 1ULL)) {
                            supp |= dt[i];
                            rem  &= ~supp;
                        }
                    }
                }
                kept = ~supp & valid;
                keep[b] = kept;
            }
            kept = __shfl_sync(0xffffffffu, kept, 0);
            carry = 0ULL;
            if (b + 1 < mb) {            // block b -> block b+1 (cross tile)
                u64 nzc = nzb_s[tsb + 1] & kept;
                if (nzc) {
                    const int cs = slot_s[tsb + 1];
                    const u64* ct = (cs < SPOOL) ? pool_s + cs * 64
                                                 : g_pool + (size_t)cs * 64;
                    u64 acc = 0ULL;
                    if ((nzc >> lane) & 1ULL)        acc |= ct[lane];
                    if ((nzc >> (lane + 32)) & 1ULL) acc |= ct[lane + 32];
                    carry = redux_or64(acc);
                }
            }
        } else if (b >= 1) {
            // Sparse lagged sweep: block b-1 -> columns j >= b+1 (smem tiles)
            const u64 kp = keep[b - 1];
            if (kp) {
                const int base = tri_start(b - 1) - (b - 1);
                for (int j = b + 1 + warp; j < mb; j += 31) {
                    u64 nz = nzb_s[base + j] & kp;      // warp-uniform
                    if (nz) {
                        const int sl = slot_s[base + j];
                        const u64* tl = (sl < SPOOL) ? pool_s + sl * 64
                                                     : g_pool + (size_t)sl * 64;
                        u64 acc = 0ULL;
                        if ((nz >> lane) & 1ULL)        acc |= tl[lane];
                        if ((nz >> (lane + 32)) & 1ULL) acc |= tl[lane + 32];
                        u64 r = redux_or64(acc);
                        if (lane == 0) atomicOr(&remv[j], r);
                    }
                }
            }
        }
        __syncthreads();
    }

    // Fused finalize: out[i] = s if (s >= 0.6 && kept) else 0
    for (int i = t; i < n; i += SCAN_THREADS) {
        float s = scores[i];
        float v = 0.0f;
        if (s >= 0.6f) {
            int r = g_rank[i];
            if ((keep[r >> 6] >> (r & 63)) & 1ULL) v = s;
        }
        out[i] = v;
    }

    if (t == 0) { g_cnt = 0; g_poolcnt = 0; }   // reset for next graph replay
}

// ---------------------------------------------------------------------------
extern "C" void kernel_launch(void* const* d_in, const int* in_sizes, int n_in,
                              void* d_out, int out_size) {
    const float* boxes  = (const float*)d_in[0];
    const float* scores = (const float*)d_in[1];
    const int n = in_sizes[1];                 // 6000

    cudaFuncSetAttribute(scan_kernel,
                         cudaFuncAttributeMaxDynamicSharedMemorySize, SMEM_BYTES);

    compact_kernel<<<(n + 255) / 256, 256>>>(scores, n);

    rank_kernel<<<(n * 32 + 255) / 256, 256>>>(boxes, n);

    mask_kernel<<<TRI, 64>>>(n);

    scan_kernel<<<1, SCAN_THREADS, SMEM_BYTES>>>(scores, (float*)d_out, n);
}